// round 16
// baseline (speedup 1.0000x reference)
#include <cuda_runtime.h>
#include <math.h>

#define W 512
#define H 512
#define HW (W*H)
#define NPTS 262144
#define RR 8
#define DD 8
#define CAP 64
#define NB 256

__device__ int       g_head[HW];
__device__ int       g_next[NPTS];
__device__ float4    g_rec[NPTS];
__device__ float     g_alpha[NPTS];
__device__ int       g_count[HW];
__device__ int       g_start[HW];
__device__ int       g_order[NPTS];
__device__ float     g_logs[NPTS];
__device__ float     g_P0[NPTS];
__device__ float     g_S1[16384];
__device__ float     g_O1[16384];
__device__ int       g_agg[NB];
__device__ int       g_flagA[NB];
__device__ int       g_done;

__global__ void init_kernel() {
    int i = blockIdx.x * blockDim.x + threadIdx.x;
    if (i < HW) { g_head[i] = -1; g_count[i] = 0; }
    if (i < NPTS) g_logs[i] = 0.0f;
    if (i < NB) g_flagA[i] = 0;
    if (i == 0) g_done = 0;
}

// 8 lanes per point: lane r handles rank r. Sequential fold orders preserved
// bitwise via width-8 shuffle gathers.
__global__ void point_kernel(const float* __restrict__ pos,
                             const float* __restrict__ trivecs,
                             const float* __restrict__ dens,
                             const float* __restrict__ shs,
                             const float* __restrict__ viewm,
                             const float* __restrict__ projm,
                             const float* __restrict__ campos,
                             const float* __restrict__ aabb)
{
    int t = blockIdx.x * blockDim.x + threadIdx.x;
    int n = t >> 3;
    int r = t & 7;
    int lane = threadIdx.x & 31;
    unsigned mask8 = 0xFFu << (lane & ~7);

    float wx = 0.f, wy = 0.f, wz = 0.f;
    if (r == 0) {
        float px = pos[3*n+0], py = pos[3*n+1], pz = pos[3*n+2];
        wx = __fadd_rn(aabb[0], __fmul_rn(px, aabb[3]));
        wy = __fadd_rn(aabb[1], __fmul_rn(py, aabb[4]));
        wz = __fadd_rn(aabb[2], __fmul_rn(pz, aabb[5]));
    }
    wx = __shfl_sync(mask8, wx, 0, 8);
    wy = __shfl_sync(mask8, wy, 0, 8);
    wz = __shfl_sync(mask8, wz, 0, 8);

    float phx = __fadd_rn(__fmaf_rn(wz, projm[8],
                 __fmaf_rn(wy, projm[4], __fmul_rn(wx, projm[0]))), projm[12]);
    float phy = __fadd_rn(__fmaf_rn(wz, projm[9],
                 __fmaf_rn(wy, projm[5], __fmul_rn(wx, projm[1]))), projm[13]);
    float phw = __fadd_rn(__fmaf_rn(wz, projm[11],
                 __fmaf_rn(wy, projm[7], __fmul_rn(wx, projm[3]))), projm[15]);
    float den = __fadd_rn(phw, 1e-7f);
    float ndcx = __fdiv_rn(phx, den);
    float ndcy = __fdiv_rn(phy, den);

    float depth = __fadd_rn(__fmaf_rn(wz, viewm[10],
                   __fmaf_rn(wy, viewm[6], __fmul_rn(wx, viewm[2]))), viewm[14]);

    float fx = rintf(__fmul_rn(__fadd_rn(__fmul_rn(__fadd_rn(ndcx, 1.0f), (float)W), -1.0f), 0.5f));
    float fy = rintf(__fmul_rn(__fadd_rn(__fmul_rn(__fadd_rn(ndcy, 1.0f), (float)H), -1.0f), 0.5f));
    int ix = (int)fx;
    int iy = (int)fy;

    bool valid = (depth > 0.2f) && (ix >= 0) && (ix < W) && (iy >= 0) && (iy < H);
    if (!valid) return;   // group-uniform

    int basetv = ((n * RR + r) * 3) * DD + DD/2;
    float m0 = __ldg(&trivecs[basetv + 0*DD]);
    float m1 = __ldg(&trivecs[basetv + 1*DD]);
    float m2 = __ldg(&trivecs[basetv + 2*DD]);
    float tri = fmaxf(__fmul_rn(__fmul_rn(m0, m1), m2), 0.0f);
    float s = __fmul_rn(expf(__fadd_rn(dens[n*RR + r], -2.0f)), tri);

    float sigma = 0.0f;
    #pragma unroll
    for (int rr = 0; rr < RR; rr++) {
        float srr = __shfl_sync(mask8, s, rr, 8);
        sigma = __fadd_rn(sigma, srr);
    }
    float tt = expf(-sigma);
    float alpha = fminf(fmaxf(__fadd_rn(1.0f, -tt), 0.0f), 0.999f);

    float dx = wx - campos[0], dy = wy - campos[1], dz = wz - campos[2];
    float nrm = sqrtf(dx*dx + dy*dy + dz*dz);
    float dn = __fadd_rn(nrm, 1e-8f);
    dx = __fdiv_rn(dx, dn); dy = __fdiv_rn(dy, dn); dz = __fdiv_rn(dz, dn);

    float basis[9];
    basis[0] = 0.28209479177387814f;
    basis[1] = -0.4886025119029199f * dy;
    basis[2] =  0.4886025119029199f * dz;
    basis[3] = -0.4886025119029199f * dx;
    basis[4] =  1.0925484305920792f * dx * dy;
    basis[5] = -1.0925484305920792f * dy * dz;
    basis[6] =  0.31539156525252005f * (2.0f*dz*dz - dx*dx - dy*dy);
    basis[7] = -1.0925484305920792f * dx * dz;
    basis[8] =  0.5462742152960396f * (dx*dx - dy*dy);

    float sden = __fadd_rn(sigma, 1e-8f);
    const float* sp = shs + (size_t)(n * RR + r) * 27;
    float ar = 0.0f, ag = 0.0f, ab = 0.0f;
    #pragma unroll
    for (int k = 0; k < 9; k++) {
        float b = basis[k];
        ar = __fmaf_rn(b, __ldg(&sp[k*3 + 0]), ar);
        ag = __fmaf_rn(b, __ldg(&sp[k*3 + 1]), ag);
        ab = __fmaf_rn(b, __ldg(&sp[k*3 + 2]), ab);
    }
    ar = fmaxf(__fadd_rn(ar, 0.5f), 0.0f);
    ag = fmaxf(__fadd_rn(ag, 0.5f), 0.0f);
    ab = fmaxf(__fadd_rn(ab, 0.5f), 0.0f);
    float wgt = __fdiv_rn(s, sden);

    float cr = 0.0f, cg = 0.0f, cb = 0.0f;
    #pragma unroll
    for (int rr = 0; rr < RR; rr++) {
        float a_ = __shfl_sync(mask8, ar, rr, 8);
        float g_ = __shfl_sync(mask8, ag, rr, 8);
        float b_ = __shfl_sync(mask8, ab, rr, 8);
        float w_ = __shfl_sync(mask8, wgt, rr, 8);
        cr = __fmaf_rn(w_, a_, cr);
        cg = __fmaf_rn(w_, g_, cg);
        cb = __fmaf_rn(w_, b_, cb);
    }

    if (r == 0) {
        g_rec[n]   = make_float4(depth, cr, cg, cb);
        g_alpha[n] = alpha;
        int pid = iy * W + ix;
        atomicAdd(&g_count[pid], 1);
        g_next[n] = atomicExch(&g_head[pid], n);
    }
}

// Fused: block scan of counts + cross-block offset (forward-only aggregate
// wait, CUB decoupled style) + per-pixel gather/sort/scatter of logs.
__global__ void __launch_bounds__(1024) scanscatter_kernel() {
    __shared__ int sm[1024];
    __shared__ int sbase;
    int tid = threadIdx.x;
    int b = blockIdx.x;
    int p = b * 1024 + tid;

    int cnt = g_count[p];
    sm[tid] = cnt;
    __syncthreads();
    for (int off = 1; off < 1024; off <<= 1) {
        int v = (tid >= off) ? sm[tid - off] : 0;
        __syncthreads(); sm[tid] += v; __syncthreads();
    }

    if (tid == 0) {
        sbase = 0;
        g_agg[b] = sm[1023];
        __threadfence();
        atomicExch(&g_flagA[b], 1);
    }
    __syncthreads();

    // wait on predecessor aggregates only (forward dependency)
    if (tid < b) {
        while (atomicAdd(&g_flagA[tid], 0) == 0) { }
        atomicAdd(&sbase, g_agg[tid]);   // int: deterministic
    }
    __syncthreads();
    int base = sbase;

    int start = base + sm[tid] - cnt;
    g_start[p] = start;
    if (cnt == 0) return;

    float dep[CAP]; int id[CAP];
    int k = 0;
    for (int node = g_head[p]; node >= 0 && k < CAP; node = g_next[node]) {
        float d = g_rec[node].x;
        int j = k;
        while (j > 0 && (dep[j-1] > d || (dep[j-1] == d && id[j-1] > node))) {
            dep[j] = dep[j-1]; id[j] = id[j-1]; j--;
        }
        dep[j] = d; id[j] = node; k++;
    }
    for (int j = 0; j < k; j++) {
        int node = id[j];
        g_order[start + j] = node;
        g_logs[start + j]  = log1pf(-g_alpha[node]);
    }
}

// Fused fold0 (16384 groups of 16) + mid scan (levels 1-3) by last-done block.
__global__ void __launch_bounds__(1024) fold0mid_kernel() {
    int tid = threadIdx.x;
    int g = blockIdx.x * 1024 + tid;     // group id
    {
        int base = g * 16;
        float acc = 0.0f;
        #pragma unroll
        for (int j = 0; j < 16; j++) {
            acc = __fadd_rn(acc, g_logs[base + j]);
            g_P0[base + j] = acc;
        }
        g_S1[g] = acc;
    }
    __threadfence();
    __shared__ int slast;
    __syncthreads();
    if (tid == 0) slast = (atomicAdd(&g_done, 1) == gridDim.x - 1);
    __syncthreads();
    if (!slast) return;

    // ---- mid scan (this block only, 1024 threads) ----
    volatile float* vS1 = g_S1;
    __shared__ float sS2[1024];
    __shared__ float sP2[1024];
    __shared__ float sO2[1024];
    __shared__ float sS3[64];
    __shared__ float sO3[64];

    float p1[16];
    {
        float acc = 0.0f;
        int base = tid * 16;
        #pragma unroll
        for (int j = 0; j < 16; j++) {
            acc = __fadd_rn(acc, vS1[base + j]);
            p1[j] = acc;
        }
        sS2[tid] = acc;
    }
    __syncthreads();

    if (tid < 64) {
        float acc = 0.0f;
        #pragma unroll
        for (int j = 0; j < 16; j++) {
            acc = __fadd_rn(acc, sS2[tid*16 + j]);
            sP2[tid*16 + j] = acc;
        }
        sS3[tid] = acc;
    }
    __syncthreads();

    if (tid == 0) {
        float P3[64], S4[4], O4[4];
        for (int bb = 0; bb < 4; bb++) {
            float acc = 0.0f;
            for (int j = 0; j < 16; j++) {
                acc = __fadd_rn(acc, sS3[bb*16 + j]);
                P3[bb*16 + j] = acc;
            }
            S4[bb] = acc;
        }
        float acc = 0.0f;
        for (int bb = 0; bb < 4; bb++) { acc = __fadd_rn(acc, S4[bb]); O4[bb] = acc; }
        for (int i = 0; i < 64; i++) {
            int bb = i >> 4;
            sO3[i] = (bb == 0) ? P3[i] : __fadd_rn(O4[bb-1], P3[i]);
        }
    }
    __syncthreads();

    {
        int bb = tid >> 4;
        sO2[tid] = (bb == 0) ? sP2[tid] : __fadd_rn(sO3[bb-1], sP2[tid]);
    }
    __syncthreads();

    {
        float carry = (tid == 0) ? 0.0f : sO2[tid-1];
        int base = tid * 16;
        #pragma unroll
        for (int j = 0; j < 16; j++) {
            g_O1[base + j] = (tid == 0) ? p1[j] : __fadd_rn(carry, p1[j]);
        }
    }
}

__device__ __forceinline__ float excl_at(int i) {
    int b = i >> 4;
    float cum = (b == 0) ? g_P0[i] : __fadd_rn(g_O1[b-1], g_P0[i]);
    return __fadd_rn(cum, -g_logs[i]);
}

__global__ void composite_kernel(float* __restrict__ out,
                                 const float* __restrict__ bg)
{
    int p = blockIdx.x * blockDim.x + threadIdx.x;
    if (p >= HW) return;
    int cnt = g_count[p];
    int s = g_start[p];

    float A = 0.0f, C0 = 0.0f, C1 = 0.0f, C2 = 0.0f, Dw = 0.0f;
    if (cnt > 0) {
        float e0 = excl_at(s);
        for (int j = 0; j < cnt; j++) {
            int slot = s + j;
            int node = g_order[slot];
            float T = expf(__fadd_rn(excl_at(slot), -e0));
            float4 rec = g_rec[node];
            float a = g_alpha[node];
            float w = __fmul_rn(a, T);
            C0 = __fmaf_rn(w, rec.y, C0);
            C1 = __fmaf_rn(w, rec.z, C1);
            C2 = __fmaf_rn(w, rec.w, C2);
            A  = __fadd_rn(A, w);
            Dw = __fmaf_rn(w, rec.x, Dw);
        }
    }
    float oneA = __fadd_rn(1.0f, -A);
    out[0*HW + p] = __fmaf_rn(oneA, bg[0], C0);
    out[1*HW + p] = __fmaf_rn(oneA, bg[1], C1);
    out[2*HW + p] = __fmaf_rn(oneA, bg[2], C2);
    out[3*HW + p] = Dw;
    out[4*HW + p] = A;
    out[5*HW + p] = __fdiv_rn(Dw, __fadd_rn(A, 1e-8f));
}

extern "C" void kernel_launch(void* const* d_in, const int* in_sizes, int n_in,
                              void* d_out, int out_size)
{
    const float* positions = (const float*)d_in[0];
    const float* trivecs   = (const float*)d_in[1];
    const float* densities = (const float*)d_in[2];
    const float* shs       = (const float*)d_in[3];
    const float* viewm     = (const float*)d_in[4];
    const float* projm     = (const float*)d_in[5];
    const float* campos    = (const float*)d_in[6];
    const float* aabb      = (const float*)d_in[7];
    const float* bg        = (const float*)d_in[8];
    float* out = (float*)d_out;

    init_kernel<<<1024, 256>>>();
    point_kernel<<<8192, 256>>>(positions, trivecs, densities, shs,
                                viewm, projm, campos, aabb);
    scanscatter_kernel<<<NB, 1024>>>();
    fold0mid_kernel<<<16, 1024>>>();
    composite_kernel<<<1024, 256>>>(out, bg);
}

// round 17
// speedup vs baseline: 1.0519x; 1.0519x over previous
#include <cuda_runtime.h>
#include <math.h>

#define W 512
#define H 512
#define HW (W*H)
#define NPTS 262144
#define RR 8
#define DD 8
#define CAP 64
#define NB 256

__device__ int       g_head[HW];
__device__ int       g_next[NPTS];
__device__ float4    g_rec[NPTS];
__device__ float     g_alpha[NPTS];
__device__ int       g_count[HW];
__device__ int       g_start[HW];
__device__ int       g_order[NPTS];
__device__ float     g_logs[NPTS];
__device__ float     g_P0[NPTS];
__device__ float     g_S1[16384];
__device__ float     g_O1[16384];
__device__ int       g_agg[NB];
__device__ int       g_flagA[NB];

__global__ void init_kernel() {
    int i = blockIdx.x * blockDim.x + threadIdx.x;
    if (i < HW) { g_head[i] = -1; g_count[i] = 0; }
    if (i < NPTS) g_logs[i] = 0.0f;
    if (i < NB) g_flagA[i] = 0;
}

// 8 lanes per point: lane r handles rank r. Sequential fold orders preserved
// bitwise via width-8 shuffle gathers.
__global__ void point_kernel(const float* __restrict__ pos,
                             const float* __restrict__ trivecs,
                             const float* __restrict__ dens,
                             const float* __restrict__ shs,
                             const float* __restrict__ viewm,
                             const float* __restrict__ projm,
                             const float* __restrict__ campos,
                             const float* __restrict__ aabb)
{
    int t = blockIdx.x * blockDim.x + threadIdx.x;
    int n = t >> 3;
    int r = t & 7;
    int lane = threadIdx.x & 31;
    unsigned mask8 = 0xFFu << (lane & ~7);

    float wx = 0.f, wy = 0.f, wz = 0.f;
    if (r == 0) {
        float px = pos[3*n+0], py = pos[3*n+1], pz = pos[3*n+2];
        wx = __fadd_rn(aabb[0], __fmul_rn(px, aabb[3]));
        wy = __fadd_rn(aabb[1], __fmul_rn(py, aabb[4]));
        wz = __fadd_rn(aabb[2], __fmul_rn(pz, aabb[5]));
    }
    wx = __shfl_sync(mask8, wx, 0, 8);
    wy = __shfl_sync(mask8, wy, 0, 8);
    wz = __shfl_sync(mask8, wz, 0, 8);

    float phx = __fadd_rn(__fmaf_rn(wz, projm[8],
                 __fmaf_rn(wy, projm[4], __fmul_rn(wx, projm[0]))), projm[12]);
    float phy = __fadd_rn(__fmaf_rn(wz, projm[9],
                 __fmaf_rn(wy, projm[5], __fmul_rn(wx, projm[1]))), projm[13]);
    float phw = __fadd_rn(__fmaf_rn(wz, projm[11],
                 __fmaf_rn(wy, projm[7], __fmul_rn(wx, projm[3]))), projm[15]);
    float den = __fadd_rn(phw, 1e-7f);
    float ndcx = __fdiv_rn(phx, den);
    float ndcy = __fdiv_rn(phy, den);

    float depth = __fadd_rn(__fmaf_rn(wz, viewm[10],
                   __fmaf_rn(wy, viewm[6], __fmul_rn(wx, viewm[2]))), viewm[14]);

    float fx = rintf(__fmul_rn(__fadd_rn(__fmul_rn(__fadd_rn(ndcx, 1.0f), (float)W), -1.0f), 0.5f));
    float fy = rintf(__fmul_rn(__fadd_rn(__fmul_rn(__fadd_rn(ndcy, 1.0f), (float)H), -1.0f), 0.5f));
    int ix = (int)fx;
    int iy = (int)fy;

    bool valid = (depth > 0.2f) && (ix >= 0) && (ix < W) && (iy >= 0) && (iy < H);
    if (!valid) return;   // group-uniform

    int basetv = ((n * RR + r) * 3) * DD + DD/2;
    float m0 = __ldg(&trivecs[basetv + 0*DD]);
    float m1 = __ldg(&trivecs[basetv + 1*DD]);
    float m2 = __ldg(&trivecs[basetv + 2*DD]);
    float tri = fmaxf(__fmul_rn(__fmul_rn(m0, m1), m2), 0.0f);
    float s = __fmul_rn(expf(__fadd_rn(dens[n*RR + r], -2.0f)), tri);

    float sigma = 0.0f;
    #pragma unroll
    for (int rr = 0; rr < RR; rr++) {
        float srr = __shfl_sync(mask8, s, rr, 8);
        sigma = __fadd_rn(sigma, srr);
    }
    float tt = expf(-sigma);
    float alpha = fminf(fmaxf(__fadd_rn(1.0f, -tt), 0.0f), 0.999f);

    float dx = wx - campos[0], dy = wy - campos[1], dz = wz - campos[2];
    float nrm = sqrtf(dx*dx + dy*dy + dz*dz);
    float dn = __fadd_rn(nrm, 1e-8f);
    dx = __fdiv_rn(dx, dn); dy = __fdiv_rn(dy, dn); dz = __fdiv_rn(dz, dn);

    float basis[9];
    basis[0] = 0.28209479177387814f;
    basis[1] = -0.4886025119029199f * dy;
    basis[2] =  0.4886025119029199f * dz;
    basis[3] = -0.4886025119029199f * dx;
    basis[4] =  1.0925484305920792f * dx * dy;
    basis[5] = -1.0925484305920792f * dy * dz;
    basis[6] =  0.31539156525252005f * (2.0f*dz*dz - dx*dx - dy*dy);
    basis[7] = -1.0925484305920792f * dx * dz;
    basis[8] =  0.5462742152960396f * (dx*dx - dy*dy);

    float sden = __fadd_rn(sigma, 1e-8f);
    const float* sp = shs + (size_t)(n * RR + r) * 27;
    float ar = 0.0f, ag = 0.0f, ab = 0.0f;
    #pragma unroll
    for (int k = 0; k < 9; k++) {
        float b = basis[k];
        ar = __fmaf_rn(b, __ldg(&sp[k*3 + 0]), ar);
        ag = __fmaf_rn(b, __ldg(&sp[k*3 + 1]), ag);
        ab = __fmaf_rn(b, __ldg(&sp[k*3 + 2]), ab);
    }
    ar = fmaxf(__fadd_rn(ar, 0.5f), 0.0f);
    ag = fmaxf(__fadd_rn(ag, 0.5f), 0.0f);
    ab = fmaxf(__fadd_rn(ab, 0.5f), 0.0f);
    float wgt = __fdiv_rn(s, sden);

    float cr = 0.0f, cg = 0.0f, cb = 0.0f;
    #pragma unroll
    for (int rr = 0; rr < RR; rr++) {
        float a_ = __shfl_sync(mask8, ar, rr, 8);
        float g_ = __shfl_sync(mask8, ag, rr, 8);
        float b_ = __shfl_sync(mask8, ab, rr, 8);
        float w_ = __shfl_sync(mask8, wgt, rr, 8);
        cr = __fmaf_rn(w_, a_, cr);
        cg = __fmaf_rn(w_, g_, cg);
        cb = __fmaf_rn(w_, b_, cb);
    }

    if (r == 0) {
        g_rec[n]   = make_float4(depth, cr, cg, cb);
        g_alpha[n] = alpha;
        int pid = iy * W + ix;
        atomicAdd(&g_count[pid], 1);
        g_next[n] = atomicExch(&g_head[pid], n);
    }
}

// Fused: block scan of counts + cross-block offset (forward-only aggregate
// wait) + per-pixel gather/sort/scatter of logs.
__global__ void __launch_bounds__(1024) scanscatter_kernel() {
    __shared__ int sm[1024];
    __shared__ int sbase;
    int tid = threadIdx.x;
    int b = blockIdx.x;
    int p = b * 1024 + tid;

    int cnt = g_count[p];
    sm[tid] = cnt;
    __syncthreads();
    for (int off = 1; off < 1024; off <<= 1) {
        int v = (tid >= off) ? sm[tid - off] : 0;
        __syncthreads(); sm[tid] += v; __syncthreads();
    }

    if (tid == 0) {
        sbase = 0;
        g_agg[b] = sm[1023];
        __threadfence();
        atomicExch(&g_flagA[b], 1);
    }
    __syncthreads();

    if (tid < b) {
        while (atomicAdd(&g_flagA[tid], 0) == 0) { }
        atomicAdd(&sbase, g_agg[tid]);
    }
    __syncthreads();
    int base = sbase;

    int start = base + sm[tid] - cnt;
    g_start[p] = start;
    if (cnt == 0) return;

    float dep[CAP]; int id[CAP];
    int k = 0;
    for (int node = g_head[p]; node >= 0 && k < CAP; node = g_next[node]) {
        float d = g_rec[node].x;
        int j = k;
        while (j > 0 && (dep[j-1] > d || (dep[j-1] == d && id[j-1] > node))) {
            dep[j] = dep[j-1]; id[j] = id[j-1]; j--;
        }
        dep[j] = d; id[j] = node; k++;
    }
    for (int j = 0; j < k; j++) {
        int node = id[j];
        g_order[start + j] = node;
        g_logs[start + j]  = log1pf(-g_alpha[node]);
    }
}

// Level 0: 16384 groups of 16 — inner leftfold prefixes + group sums (wide grid)
__global__ void fold0() {
    int b = blockIdx.x * blockDim.x + threadIdx.x;
    if (b >= 16384) return;
    int base = b * 16;
    float acc = 0.0f;
    #pragma unroll
    for (int j = 0; j < 16; j++) {
        acc = __fadd_rn(acc, g_logs[base + j]);
        g_P0[base + j] = acc;
    }
    g_S1[b] = acc;
}

// Merged levels 1..3 + combines 2,1: single block, 1024 threads.
__global__ void scan_mid() {
    __shared__ float sS2[1024];
    __shared__ float sP2[1024];
    __shared__ float sO2[1024];
    __shared__ float sS3[64];
    __shared__ float sO3[64];
    int tid = threadIdx.x;

    float p1[16];
    {
        float acc = 0.0f;
        int base = tid * 16;
        #pragma unroll
        for (int j = 0; j < 16; j++) {
            acc = __fadd_rn(acc, g_S1[base + j]);
            p1[j] = acc;
        }
        sS2[tid] = acc;
    }
    __syncthreads();

    if (tid < 64) {
        float acc = 0.0f;
        #pragma unroll
        for (int j = 0; j < 16; j++) {
            acc = __fadd_rn(acc, sS2[tid*16 + j]);
            sP2[tid*16 + j] = acc;
        }
        sS3[tid] = acc;
    }
    __syncthreads();

    if (tid == 0) {
        float P3[64], S4[4], O4[4];
        for (int bb = 0; bb < 4; bb++) {
            float acc = 0.0f;
            for (int j = 0; j < 16; j++) {
                acc = __fadd_rn(acc, sS3[bb*16 + j]);
                P3[bb*16 + j] = acc;
            }
            S4[bb] = acc;
        }
        float acc = 0.0f;
        for (int bb = 0; bb < 4; bb++) { acc = __fadd_rn(acc, S4[bb]); O4[bb] = acc; }
        for (int i = 0; i < 64; i++) {
            int bb = i >> 4;
            sO3[i] = (bb == 0) ? P3[i] : __fadd_rn(O4[bb-1], P3[i]);
        }
    }
    __syncthreads();

    {
        int bb = tid >> 4;
        sO2[tid] = (bb == 0) ? sP2[tid] : __fadd_rn(sO3[bb-1], sP2[tid]);
    }
    __syncthreads();

    {
        float carry = (tid == 0) ? 0.0f : sO2[tid-1];
        int base = tid * 16;
        #pragma unroll
        for (int j = 0; j < 16; j++) {
            g_O1[base + j] = (tid == 0) ? p1[j] : __fadd_rn(carry, p1[j]);
        }
    }
}

__device__ __forceinline__ float excl_at(int i) {
    int b = i >> 4;
    float cum = (b == 0) ? g_P0[i] : __fadd_rn(g_O1[b-1], g_P0[i]);
    return __fadd_rn(cum, -g_logs[i]);
}

__global__ void composite_kernel(float* __restrict__ out,
                                 const float* __restrict__ bg)
{
    int p = blockIdx.x * blockDim.x + threadIdx.x;
    if (p >= HW) return;
    int cnt = g_count[p];
    int s = g_start[p];

    float A = 0.0f, C0 = 0.0f, C1 = 0.0f, C2 = 0.0f, Dw = 0.0f;
    if (cnt > 0) {
        float e0 = excl_at(s);
        for (int j = 0; j < cnt; j++) {
            int slot = s + j;
            int node = g_order[slot];
            float T = expf(__fadd_rn(excl_at(slot), -e0));
            float4 rec = g_rec[node];
            float a = g_alpha[node];
            float w = __fmul_rn(a, T);
            C0 = __fmaf_rn(w, rec.y, C0);
            C1 = __fmaf_rn(w, rec.z, C1);
            C2 = __fmaf_rn(w, rec.w, C2);
            A  = __fadd_rn(A, w);
            Dw = __fmaf_rn(w, rec.x, Dw);
        }
    }
    float oneA = __fadd_rn(1.0f, -A);
    out[0*HW + p] = __fmaf_rn(oneA, bg[0], C0);
    out[1*HW + p] = __fmaf_rn(oneA, bg[1], C1);
    out[2*HW + p] = __fmaf_rn(oneA, bg[2], C2);
    out[3*HW + p] = Dw;
    out[4*HW + p] = A;
    out[5*HW + p] = __fdiv_rn(Dw, __fadd_rn(A, 1e-8f));
}

extern "C" void kernel_launch(void* const* d_in, const int* in_sizes, int n_in,
                              void* d_out, int out_size)
{
    const float* positions = (const float*)d_in[0];
    const float* trivecs   = (const float*)d_in[1];
    const float* densities = (const float*)d_in[2];
    const float* shs       = (const float*)d_in[3];
    const float* viewm     = (const float*)d_in[4];
    const float* projm     = (const float*)d_in[5];
    const float* campos    = (const float*)d_in[6];
    const float* aabb      = (const float*)d_in[7];
    const float* bg        = (const float*)d_in[8];
    float* out = (float*)d_out;

    init_kernel<<<1024, 256>>>();
    point_kernel<<<8192, 256>>>(positions, trivecs, densities, shs,
                                viewm, projm, campos, aabb);
    scanscatter_kernel<<<NB, 1024>>>();
    fold0<<<64, 256>>>();
    scan_mid<<<1, 1024>>>();
    composite_kernel<<<1024, 256>>>(out, bg);
}